// round 17
// baseline (speedup 1.0000x reference)
#include <cuda_runtime.h>
#include <cuda_fp16.h>
#include <math.h>

#define N_NODES 8000
#define N_EDGES 256000
#define F0      512

// ---------------- scratch (static device allocations; no cudaMalloc) --------
__device__ float g_w    [2][N_EDGES];
__device__ float g_dinv [2][N_NODES];
__device__ int   g_hist [2][N_NODES];
__device__ int   g_offs [2][N_NODES + 1];
__device__ int   g_fill [2][N_NODES];
__device__ int   g_crow [2][N_EDGES];
__device__ float g_ccoef[2][N_EDGES];
// fp16 tensors (whole dataflow is fp16)
__device__ __half g_xh [2][N_NODES * F0];
__device__ __half g_th [2][N_NODES * F0];   // GCN GEMM output (pre-aggregation)
__device__ __half g_hh [2][N_NODES * F0];   // aggregation output
__device__ __half g_w1h[2][F0 * F0];
__device__ __half g_w2h[2][F0 * F0];
__device__ __half g_l1h[2][F0 * 256];
__device__ __half g_l2h[2][256 * 128];
__device__ __half g_l3h[2][128 * 64 + 64];  // +64 pad: B prefetch reads 128 cols
__device__ __half g_m1h[2][N_NODES * 256];
__device__ __half g_m2h[2][N_NODES * 128];
__device__ __half g_m3h[2][N_NODES * 64];

// ---------------- fp32 -> fp16 conversions -----------------------------------
__global__ void conv_x_kernel(const float* __restrict__ s0, const float* __restrict__ s1) {
    int i = (blockIdx.x * blockDim.x + threadIdx.x) * 4;
    int g = blockIdx.y;
    const float* s = g ? s1 : s0;
    if (i < N_NODES * F0) {
        float4 v = *reinterpret_cast<const float4*>(&s[i]);
        __half2 h0 = __floats2half2_rn(v.x, v.y);
        __half2 h1 = __floats2half2_rn(v.z, v.w);
        *reinterpret_cast<uint2*>(&g_xh[g][i]) =
            make_uint2(*reinterpret_cast<unsigned*>(&h0), *reinterpret_cast<unsigned*>(&h1));
    }
}

// z = 0:W1, 1:W2, 2:L1w, 3:L2w, 4:L3w   (kept [K][N] layout, fp16)
__global__ void conv_w_kernel(const float* __restrict__ w10, const float* __restrict__ w11,
                              const float* __restrict__ w20, const float* __restrict__ w21,
                              const float* __restrict__ l10, const float* __restrict__ l11,
                              const float* __restrict__ l20, const float* __restrict__ l21,
                              const float* __restrict__ l30, const float* __restrict__ l31) {
    int i = (blockIdx.x * blockDim.x + threadIdx.x) * 4;
    int g = blockIdx.y;
    int z = blockIdx.z;
    int n = (z <= 1) ? F0 * F0 : (z == 2) ? F0 * 256 : (z == 3) ? 256 * 128 : 128 * 64;
    const float* s =
        (z == 0) ? (g ? w11 : w10) : (z == 1) ? (g ? w21 : w20) :
        (z == 2) ? (g ? l11 : l10) : (z == 3) ? (g ? l21 : l20) : (g ? l31 : l30);
    __half* d = (z == 0) ? g_w1h[g] : (z == 1) ? g_w2h[g] :
                (z == 2) ? g_l1h[g] : (z == 3) ? g_l2h[g] : g_l3h[g];
    if (i < n) {
        float4 v = *reinterpret_cast<const float4*>(&s[i]);
        __half2 h0 = __floats2half2_rn(v.x, v.y);
        __half2 h1 = __floats2half2_rn(v.z, v.w);
        *reinterpret_cast<uint2*>(&d[i]) =
            make_uint2(*reinterpret_cast<unsigned*>(&h0), *reinterpret_cast<unsigned*>(&h1));
    }
}

// ---------------- edge / degree prep (both graphs batched: blockIdx.y = g) --
__global__ void init_kernel() {
    int i = blockIdx.x * blockDim.x + threadIdx.x;
    int g = blockIdx.y;
    if (i < N_NODES) { g_dinv[g][i] = 1.0f; g_hist[g][i] = 0; }
}

__global__ void edge_kernel(const float* __restrict__ d0, const float* __restrict__ d1,
                            const int* __restrict__ e0, const int* __restrict__ e1) {
    int e = blockIdx.x * blockDim.x + threadIdx.x;
    int g = blockIdx.y;
    const float* data = g ? d1 : d0;
    const int*   ei   = g ? e1 : e0;
    if (e < N_EDGES) {
        int r = ei[e];
        int c = ei[N_EDGES + e];
        float v = fmaxf(data[(size_t)r * N_NODES + c], 0.0f);
        g_w[g][e] = v;
        atomicAdd(&g_dinv[g][c], v);
        atomicAdd(&g_hist[g][c], 1);
    }
}

__global__ void scan_dinv_kernel() {
    __shared__ int s[1024];
    int g = blockIdx.x;
    int t = threadIdx.x;
    for (int i = t; i < N_NODES; i += 1024)
        g_dinv[g][i] = rsqrtf(g_dinv[g][i]);
    int base = t * 8;
    int loc[8];
    int sum = 0;
#pragma unroll
    for (int j = 0; j < 8; j++) {
        int i = base + j;
        int v = (i < N_NODES) ? g_hist[g][i] : 0;
        loc[j] = sum;
        sum += v;
    }
    s[t] = sum;
    __syncthreads();
    for (int d = 1; d < 1024; d <<= 1) {
        int v = (t >= d) ? s[t - d] : 0;
        __syncthreads();
        s[t] += v;
        __syncthreads();
    }
    int cbase = s[t] - sum;
#pragma unroll
    for (int j = 0; j < 8; j++) {
        int i = base + j;
        if (i < N_NODES) {
            int o = cbase + loc[j];
            g_offs[g][i] = o;
            g_fill[g][i] = o;
        }
    }
    if (t == 0) g_offs[g][N_NODES] = N_EDGES;
}

__global__ void scatter_coeff_kernel(const int* __restrict__ e0, const int* __restrict__ e1) {
    int e = blockIdx.x * blockDim.x + threadIdx.x;
    int g = blockIdx.y;
    const int* ei = g ? e1 : e0;
    if (e < N_EDGES) {
        int r = ei[e];
        int c = ei[N_EDGES + e];
        float cf = g_dinv[g][r] * g_w[g][e] * g_dinv[g][c];
        int p = atomicAdd(&g_fill[g][c], 1);
        g_crow[g][p]  = r;
        g_ccoef[g][p] = cf;
    }
}

// ---------------- GCN aggregation (fp16 gather, fp32 accum, fp16 out) --------
__global__ void aggregate_kernel(const float* __restrict__ bias0,
                                 const float* __restrict__ bias1) {
    int c = blockIdx.x;
    int g = blockIdx.y;
    const float* bias = g ? bias1 : bias0;
    const __half* __restrict__ th = g_th[g];
    __half* outh = g_hh[g];
    const int* __restrict__ crow = g_crow[g];
    const float* __restrict__ ccoef = g_ccoef[g];
    int f = threadIdx.x * 4;
    float dv = g_dinv[g][c];
    float sc = dv * dv;
    uint2 sraw = *reinterpret_cast<const uint2*>(&th[(size_t)c * F0 + f]);
    float2 s0 = __half22float2(*reinterpret_cast<__half2*>(&sraw.x));
    float2 s1 = __half22float2(*reinterpret_cast<__half2*>(&sraw.y));
    float4 acc = make_float4(s0.x * sc, s0.y * sc, s1.x * sc, s1.y * sc);
    int e0 = g_offs[g][c], e1 = g_offs[g][c + 1];
#pragma unroll 8
    for (int e = e0; e < e1; e++) {
        int   r  = crow[e];
        float cf = ccoef[e];
        uint2 raw = *reinterpret_cast<const uint2*>(&th[(size_t)r * F0 + f]);
        float2 u0 = __half22float2(*reinterpret_cast<__half2*>(&raw.x));
        float2 u1 = __half22float2(*reinterpret_cast<__half2*>(&raw.y));
        acc.x += cf * u0.x; acc.y += cf * u0.y;
        acc.z += cf * u1.x; acc.w += cf * u1.y;
    }
    float4 b = *reinterpret_cast<const float4*>(&bias[f]);
    acc.x = fmaxf(acc.x + b.x, 0.0f);
    acc.y = fmaxf(acc.y + b.y, 0.0f);
    acc.z = fmaxf(acc.z + b.z, 0.0f);
    acc.w = fmaxf(acc.w + b.w, 0.0f);
    __half2 h0 = __floats2half2_rn(acc.x, acc.y);
    __half2 h1 = __floats2half2_rn(acc.z, acc.w);
    *reinterpret_cast<uint2*>(&outh[(size_t)c * F0 + f]) =
        make_uint2(*reinterpret_cast<unsigned*>(&h0), *reinterpret_cast<unsigned*>(&h1));
}

// ---------------- FP16 tensor-core GEMM (BK=64, 3-stage cp.async pipeline) ---
// 128x128x64 tile, 256 threads, 3-stage SMEM ring, cp.async + ldmatrix.
// C[Mn,Nn] = A[Mn,Kn] @ B  (B is [Kn,Nn] if !TRANSB else [Nn,Kn]); Kn % 64 == 0.
// OUTM: 0 = fp32 C, 1 = fp16 C.
// Dynamic smem: 3 x (A 18KB + B <=18KB) = 108KB; 2 CTAs/SM = 216KB <= 227KB.
#define GEMM_SMEM_BYTES 110592

__device__ __forceinline__ void ldsm_x4(unsigned& r0, unsigned& r1,
                                        unsigned& r2, unsigned& r3, unsigned addr) {
    asm volatile("ldmatrix.sync.aligned.m8n8.x4.shared.b16 {%0,%1,%2,%3}, [%4];"
                 : "=r"(r0), "=r"(r1), "=r"(r2), "=r"(r3) : "r"(addr));
}
__device__ __forceinline__ void ldsm_x4_trans(unsigned& r0, unsigned& r1,
                                              unsigned& r2, unsigned& r3, unsigned addr) {
    asm volatile("ldmatrix.sync.aligned.m8n8.x4.trans.shared.b16 {%0,%1,%2,%3}, [%4];"
                 : "=r"(r0), "=r"(r1), "=r"(r2), "=r"(r3) : "r"(addr));
}
__device__ __forceinline__ void cpasync16(unsigned dst, const void* src) {
    asm volatile("cp.async.cg.shared.global [%0], [%1], 16;" :: "r"(dst), "l"(src));
}

template <bool TRANSB, bool BIAS, bool RELU, int OUTM>
__global__ __launch_bounds__(256, 2)
void fp16_gemm(const __half* __restrict__ A0, const __half* __restrict__ A1,
               const __half* __restrict__ B0, const __half* __restrict__ B1,
               const float* __restrict__ bias0, const float* __restrict__ bias1,
               void* __restrict__ C0v, void* __restrict__ C1v,
               int Mn, int Nn, int Kn) {
    constexpr int BM = 128, BN = 128, BK = 64;
    constexpr int LDA  = BK / 2 + 4;  // 36 words = 144B rows: conflict-free
    constexpr int LDB2 = BK / 2 + 4;  // TRANSB: same layout as A
    constexpr int LDBH = BN + 8;      // !TRANSB: [k][n] halves, 272B rows
    constexpr int ASZ = BM * LDA;                                // words (4608)
    constexpr int BSZ = TRANSB ? (BN * LDB2) : (BK * LDBH / 2);  // words
    extern __shared__ __align__(16) unsigned dsm[];

    const int gsel = blockIdx.z;
    const __half* A   = gsel ? A1 : A0;
    const __half* B   = gsel ? B1 : B0;
    const float* bias = gsel ? bias1 : bias0;
    void*        Cv   = gsel ? C1v : C0v;

    const int tid  = threadIdx.x;
    const int lane = tid & 31;
    const int wid  = tid >> 5;
    const int wm   = (wid & 1) * 64;
    const int wn   = (wid >> 1) * 32;
    const int q    = lane >> 2;
    const int r    = lane & 3;
    const int m0   = blockIdx.y * BM;
    const int n0   = blockIdx.x * BN;

    const int la_row  = ((lane >> 3) & 1) * 8 + (lane & 7);
    const int la_koff = ((lane >> 4) & 1) * 4;
    const int lbt_row = ((lane >> 4) & 1) * 8 + (lane & 7);
    const int lbt_koff= ((lane >> 3) & 1) * 4;
    const int lbn_k   = ((lane >> 3) & 1) * 8 + (lane & 7);
    const int lbn_n   = ((lane >> 4) & 1) * 8;

    const unsigned smem0   = (unsigned)__cvta_generic_to_shared(dsm);
    const unsigned as_base = smem0;
    const unsigned bs_base = smem0 + 3 * ASZ * 4;

    float c[4][4][4];
#pragma unroll
    for (int i = 0; i < 4; i++)
#pragma unroll
        for (int j = 0; j < 4; j++)
#pragma unroll
            for (int k = 0; k < 4; k++) c[i][j][k] = 0.0f;

    auto prefetchA = [&](int st, int k0) {
        unsigned dstb = as_base + st * ASZ * 4;
#pragma unroll
        for (int i = 0; i < 4; i++) {
            int p = tid + i * 256;
            int row = p >> 3;
            int ch  = p & 7;
            int gr = m0 + row; if (gr > Mn - 1) gr = Mn - 1;
            cpasync16(dstb + (unsigned)(row * 144 + ch * 16),
                      A + (size_t)gr * Kn + k0 + ch * 8);
        }
    };
    auto prefetchB = [&](int st, int k0) {
        unsigned dstb = bs_base + st * BSZ * 4;
        if (!TRANSB) {
#pragma unroll
            for (int i = 0; i < 4; i++) {
                int p  = tid + i * 256;
                int kp = p >> 4;
                int ch = p & 15;
                cpasync16(dstb + (unsigned)(kp * 272 + ch * 16),
                          B + (size_t)(k0 + kp) * Nn + n0 + ch * 8);
            }
        } else {
#pragma unroll
            for (int i = 0; i < 4; i++) {
                int p = tid + i * 256;
                int row = p >> 3;
                int ch  = p & 7;
                int gn = n0 + row; if (gn > Nn - 1) gn = Nn - 1;
                cpasync16(dstb + (unsigned)(row * 144 + ch * 16),
                          B + (size_t)gn * Kn + k0 + ch * 8);
            }
        }
    };
    auto compute = [&](int st) {
        const unsigned a_st = as_base + st * ASZ * 4;
        const unsigned b_st = bs_base + st * BSZ * 4;
#pragma unroll
        for (int half = 0; half < 2; half++) {
            unsigned a[2][4][4], b[2][4][2];
#pragma unroll
            for (int hh = 0; hh < 2; hh++) {
                int ks = half * 16 + hh * 8;
#pragma unroll
                for (int tm = 0; tm < 4; tm++) {
                    unsigned addr = a_st +
                        ((unsigned)((wm + tm * 16 + la_row) * LDA + ks + la_koff) << 2);
                    ldsm_x4(a[hh][tm][0], a[hh][tm][1], a[hh][tm][2], a[hh][tm][3], addr);
                }
                if (!TRANSB) {
#pragma unroll
                    for (int tp = 0; tp < 2; tp++) {
                        unsigned addr = b_st +
                            ((unsigned)((2 * ks + lbn_k) * LDBH + wn + tp * 16 + lbn_n) << 1);
                        ldsm_x4_trans(b[hh][2 * tp][0], b[hh][2 * tp][1],
                                      b[hh][2 * tp + 1][0], b[hh][2 * tp + 1][1], addr);
                    }
                } else {
#pragma unroll
                    for (int tp = 0; tp < 2; tp++) {
                        unsigned addr = b_st +
                            ((unsigned)((wn + tp * 16 + lbt_row) * LDB2 + ks + lbt_koff) << 2);
                        ldsm_x4(b[hh][2 * tp][0], b[hh][2 * tp][1],
                                b[hh][2 * tp + 1][0], b[hh][2 * tp + 1][1], addr);
                    }
                }
            }
#pragma unroll
            for (int hh = 0; hh < 2; hh++)
#pragma unroll
                for (int tm = 0; tm < 4; tm++)
#pragma unroll
                    for (int tn = 0; tn < 4; tn++) {
                        asm volatile(
                            "mma.sync.aligned.m16n8k16.row.col.f32.f16.f16.f32 "
                            "{%0,%1,%2,%3}, {%4,%5,%6,%7}, {%8,%9}, {%0,%1,%2,%3};"
                            : "+f"(c[tm][tn][0]), "+f"(c[tm][tn][1]),
                              "+f"(c[tm][tn][2]), "+f"(c[tm][tn][3])
                            : "r"(a[hh][tm][0]), "r"(a[hh][tm][1]),
                              "r"(a[hh][tm][2]), "r"(a[hh][tm][3]),
                              "r"(b[hh][tn][0]), "r"(b[hh][tn][1]));
                    }
        }
    };

    const int nT = Kn / BK;
    // prologue: fill up to 2 stages
    prefetchA(0, 0);
    prefetchB(0, 0);
    asm volatile("cp.async.commit_group;");
    if (nT > 1) {
        prefetchA(1, BK);
        prefetchB(1, BK);
        asm volatile("cp.async.commit_group;");
    }

    for (int i = 0; i < nT; i++) {
        int s = i % 3;
        if (i + 1 < nT) asm volatile("cp.async.wait_group 1;");
        else            asm volatile("cp.async.wait_group 0;");
        __syncthreads();
        if (i + 2 < nT) {
            int st = (i + 2) % 3;
            prefetchA(st, (i + 2) * BK);
            prefetchB(st, (i + 2) * BK);
            asm volatile("cp.async.commit_group;");
        }
        compute(s);
    }

    // epilogue
#pragma unroll
    for (int tm = 0; tm < 4; tm++) {
        int row = m0 + wm + tm * 16 + q;
#pragma unroll
        for (int tn = 0; tn < 4; tn++) {
            int col = n0 + wn + tn * 8 + 2 * r;
            if (col >= Nn) continue;
            float v0 = c[tm][tn][0], v1 = c[tm][tn][1];
            float v2 = c[tm][tn][2], v3 = c[tm][tn][3];
            if (BIAS) {
                float bb0 = bias[col], bb1 = bias[col + 1];
                v0 += bb0; v1 += bb1; v2 += bb0; v3 += bb1;
            }
            if (RELU) {
                v0 = fmaxf(v0, 0.f); v1 = fmaxf(v1, 0.f);
                v2 = fmaxf(v2, 0.f); v3 = fmaxf(v3, 0.f);
            }
            if (OUTM == 0) {
                float* Cf = reinterpret_cast<float*>(Cv);
                if (row < Mn)
                    *reinterpret_cast<float2*>(&Cf[(size_t)row * Nn + col]) = make_float2(v0, v1);
                if (row + 8 < Mn)
                    *reinterpret_cast<float2*>(&Cf[(size_t)(row + 8) * Nn + col]) = make_float2(v2, v3);
            } else {
                __half* Ch = reinterpret_cast<__half*>(Cv);
                if (row < Mn) {
                    __half2 p = __floats2half2_rn(v0, v1);
                    *reinterpret_cast<unsigned*>(&Ch[(size_t)row * Nn + col]) =
                        *reinterpret_cast<unsigned*>(&p);
                }
                if (row + 8 < Mn) {
                    __half2 p = __floats2half2_rn(v2, v3);
                    *reinterpret_cast<unsigned*>(&Ch[(size_t)(row + 8) * Nn + col]) =
                        *reinterpret_cast<unsigned*>(&p);
                }
            }
        }
    }
}

// ---------------- host-side orchestration -----------------------------------
extern "C" void kernel_launch(void* const* d_in, const int* in_sizes, int n_in,
                              void* d_out, int out_size) {
    const float* x_in[2]  = { (const float*)d_in[0], (const float*)d_in[1] };
    const float* dmat[2]  = { (const float*)d_in[2], (const float*)d_in[3] };
    const int*   ei[2]    = { (const int*)d_in[4],   (const int*)d_in[5]   };
    const float* W1[2]    = { (const float*)d_in[6],  (const float*)d_in[10] };
    const float* b1[2]    = { (const float*)d_in[7],  (const float*)d_in[11] };
    const float* W2[2]    = { (const float*)d_in[8],  (const float*)d_in[12] };
    const float* b2[2]    = { (const float*)d_in[9],  (const float*)d_in[13] };
    const float* L1w[2]   = { (const float*)d_in[14], (const float*)d_in[20] };
    const float* L1b[2]   = { (const float*)d_in[15], (const float*)d_in[21] };
    const float* L2w[2]   = { (const float*)d_in[16], (const float*)d_in[22] };
    const float* L2b[2]   = { (const float*)d_in[17], (const float*)d_in[23] };
    const float* L3w[2]   = { (const float*)d_in[18], (const float*)d_in[24] };
    const float* L3b[2]   = { (const float*)d_in[19], (const float*)d_in[25] };
    float* out = (float*)d_out;

    __half *p_xh, *p_th, *p_hh, *p_w1h, *p_w2h, *p_l1h, *p_l2h, *p_l3h;
    __half *p_m1h, *p_m2h, *p_m3h;
    cudaGetSymbolAddress((void**)&p_xh,  g_xh);
    cudaGetSymbolAddress((void**)&p_th,  g_th);
    cudaGetSymbolAddress((void**)&p_hh,  g_hh);
    cudaGetSymbolAddress((void**)&p_w1h, g_w1h);
    cudaGetSymbolAddress((void**)&p_w2h, g_w2h);
    cudaGetSymbolAddress((void**)&p_l1h, g_l1h);
    cudaGetSymbolAddress((void**)&p_l2h, g_l2h);
    cudaGetSymbolAddress((void**)&p_l3h, g_l3h);
    cudaGetSymbolAddress((void**)&p_m1h, g_m1h);
    cudaGetSymbolAddress((void**)&p_m2h, g_m2h);
    cudaGetSymbolAddress((void**)&p_m3h, g_m3h);

    __half* xh[2]  = { p_xh,  p_xh  + (size_t)N_NODES * F0 };
    __half* th[2]  = { p_th,  p_th  + (size_t)N_NODES * F0 };
    __half* hh[2]  = { p_hh,  p_hh  + (size_t)N_NODES * F0 };
    __half* w1h[2] = { p_w1h, p_w1h + (size_t)F0 * F0 };
    __half* w2h[2] = { p_w2h, p_w2h + (size_t)F0 * F0 };
    __half* l1h[2] = { p_l1h, p_l1h + (size_t)F0 * 256 };
    __half* l2h[2] = { p_l2h, p_l2h + (size_t)256 * 128 };
    __half* l3h[2] = { p_l3h, p_l3h + (size_t)(128 * 64 + 64) };
    __half* m1h[2] = { p_m1h, p_m1h + (size_t)N_NODES * 256 };
    __half* m2h[2] = { p_m2h, p_m2h + (size_t)N_NODES * 128 };
    __half* m3h[2] = { p_m3h, p_m3h + (size_t)N_NODES * 64 };

    // opt-in to 108KB dynamic SMEM (idempotent)
    cudaFuncSetAttribute(fp16_gemm<false, false, false, 1>,
                         cudaFuncAttributeMaxDynamicSharedMemorySize, GEMM_SMEM_BYTES);
    cudaFuncSetAttribute(fp16_gemm<false, true, true, 1>,
                         cudaFuncAttributeMaxDynamicSharedMemorySize, GEMM_SMEM_BYTES);
    cudaFuncSetAttribute(fp16_gemm<true, false, false, 0>,
                         cudaFuncAttributeMaxDynamicSharedMemorySize, GEMM_SMEM_BYTES);

    const int TB = 256;
    const dim3 gN((N_NODES + TB - 1) / TB, 2);
    const dim3 gE((N_EDGES + TB - 1) / TB, 2);
    const int MB = (N_NODES + 127) / 128;   // 63

    // 1-3: conversions + init (GEMM1 deps first so ncu slot 4 = fp16_gemm)
    conv_x_kernel<<<dim3((N_NODES * F0 / 4 + TB - 1) / TB, 2), TB>>>(x_in[0], x_in[1]);
    conv_w_kernel<<<dim3((F0 * F0 / 4 + TB - 1) / TB, 2, 5), TB>>>(
        W1[0], W1[1], W2[0], W2[1], L1w[0], L1w[1], L2w[0], L2w[1], L3w[0], L3w[1]);
    init_kernel<<<gN, TB>>>();

    // 4 (ncu capture slot): GCN layer-1 GEMM  th = fp16(x @ W1)
    fp16_gemm<false, false, false, 1><<<dim3(F0 / 128, MB, 2), 256, GEMM_SMEM_BYTES>>>(
        xh[0], xh[1], w1h[0], w1h[1], nullptr, nullptr, th[0], th[1],
        N_NODES, F0, F0);

    // finish edge prep
    edge_kernel<<<gE, TB>>>(dmat[0], dmat[1], ei[0], ei[1]);
    scan_dinv_kernel<<<2, 1024>>>();
    scatter_coeff_kernel<<<gE, TB>>>(ei[0], ei[1]);

    // agg1: hh = fp16(relu(agg(th) + b1))
    aggregate_kernel<<<dim3(N_NODES, 2), 128>>>(b1[0], b1[1]);

    // GCN layer 2
    fp16_gemm<false, false, false, 1><<<dim3(F0 / 128, MB, 2), 256, GEMM_SMEM_BYTES>>>(
        hh[0], hh[1], w2h[0], w2h[1], nullptr, nullptr, th[0], th[1],
        N_NODES, F0, F0);
    aggregate_kernel<<<dim3(N_NODES, 2), 128>>>(b2[0], b2[1]);

    // MLP (all fp16 tensor-core): 512->256->128->64
    fp16_gemm<false, true, true, 1><<<dim3(2, MB, 2), 256, GEMM_SMEM_BYTES>>>(
        hh[0], hh[1], l1h[0], l1h[1], L1b[0], L1b[1], m1h[0], m1h[1],
        N_NODES, 256, F0);
    fp16_gemm<false, true, true, 1><<<dim3(1, MB, 2), 256, GEMM_SMEM_BYTES>>>(
        m1h[0], m1h[1], l2h[0], l2h[1], L2b[0], L2b[1], m2h[0], m2h[1],
        N_NODES, 128, 256);
    fp16_gemm<false, true, true, 1><<<dim3(1, MB, 2), 256, GEMM_SMEM_BYTES>>>(
        m2h[0], m2h[1], l3h[0], l3h[1], L3b[0], L3b[1], m3h[0], m3h[1],
        N_NODES, 64, 128);

    // final (TRANSB): out = x64_m @ y64_d^T  [8000 x 8000]
    fp16_gemm<true, false, false, 0><<<dim3(MB, MB, 1), 256, GEMM_SMEM_BYTES>>>(
        m3h[0], m3h[0], m3h[1], m3h[1], nullptr, nullptr, out, out,
        N_NODES, N_NODES, 64);
}